// round 1
// baseline (speedup 1.0000x reference)
#include <cuda_runtime.h>

#define NN 100000
#define NE 1600000
#define NG 128

// ---- scratch (device globals; no allocation allowed) ----
__device__ float d_deg[NN];
__device__ float d_dinv[NN];
__device__ float d_g1[NN * 64];     // dinv[i] * (x@W1)[i]
__device__ float d_acc1[NN * 64];   // conv1 accumulator
__device__ float d_g2[NN * 128];    // dinv[i] * (h1@W2)[i]
__device__ float d_acc2[NN * 128];  // conv2 accumulator
__device__ float d_cnt[NG];
__device__ int   d_idx64;           // 1 if indices are int64, 0 if int32

// ---- runtime index-width probe ----
// If the data is really int32, an int64 view combines two random values in
// [0,1e5): the high half is nonzero w.p. ~(1-1e-5), so value >= 2^32.
__global__ void k_probe(const void* __restrict__ ei) {
    if (threadIdx.x == 0 && blockIdx.x == 0) {
        const long long* p = (const long long*)ei;
        int ok = 1;
        for (int i = 0; i < 16; i++) {
            long long v = p[i];
            if (v < 0 || v >= NN) ok = 0;
        }
        d_idx64 = ok;
    }
}

__device__ __forceinline__ int load_idx(const void* p, long long i) {
    if (d_idx64) return (int)((const long long*)p)[i];
    return ((const int*)p)[i];
}

// ---- K1: deg = 1 (self loop) ----
__global__ void k_init_deg() {
    int i = blockIdx.x * blockDim.x + threadIdx.x;
    if (i < NN) d_deg[i] = 1.0f;
}

// ---- K2: in-degree count ----
__global__ void k_deg(const void* __restrict__ ei) {
    int e = blockIdx.x * blockDim.x + threadIdx.x;
    if (e < NE) {
        int dst = load_idx(ei, (long long)NE + e);
        atomicAdd(&d_deg[dst], 1.0f);
    }
}

// ---- K3: dinv, g1 = dinv*(x@W1), acc1 = dinv*g1 (self-loop term) ----
// 256 threads = 4 nodes x 64 cols
__global__ void k_node1(const float* __restrict__ x, const float* __restrict__ W1) {
    __shared__ float sW[192];
    int tid = threadIdx.x;
    if (tid < 192) sW[tid] = W1[tid];
    __syncthreads();
    int node = blockIdx.x * 4 + (tid >> 6);
    int c = tid & 63;
    float x0 = x[node * 3], x1 = x[node * 3 + 1], x2 = x[node * 3 + 2];
    float h = fmaf(x0, sW[c], fmaf(x1, sW[64 + c], x2 * sW[128 + c]));
    float di = rsqrtf(d_deg[node]);
    if (c == 0) d_dinv[node] = di;
    float g = di * h;
    d_g1[(size_t)node * 64 + c] = g;
    d_acc1[(size_t)node * 64 + c] = di * g;
}

// ---- K4: edge scatter, 64 feats. 16 threads/edge, one float4 each ----
__global__ void k_edge64(const void* __restrict__ ei) {
    long long t = (long long)blockIdx.x * blockDim.x + threadIdx.x;
    int e = (int)(t >> 4);
    int q = (int)(t & 15);
    if (e >= NE) return;
    int src = load_idx(ei, e);
    int dst = load_idx(ei, (long long)NE + e);
    float nd = d_dinv[dst];
    const float4* gp = (const float4*)(d_g1 + (size_t)src * 64);
    float4 v = gp[q];
    float* ap = d_acc1 + (size_t)dst * 64 + q * 4;
    asm volatile("red.global.add.v4.f32 [%0], {%1,%2,%3,%4};"
                 :: "l"(ap), "f"(v.x * nd), "f"(v.y * nd), "f"(v.z * nd), "f"(v.w * nd)
                 : "memory");
}

// ---- K5: h1=relu(acc1+b1); h2lin=h1@W2; g2=dinv*h2lin; acc2=dinv*g2 ----
// 256 threads: 8 warps, one node per warp; W2 (64x128) staged in shared.
__global__ void k_node2(const float* __restrict__ W2, const float* __restrict__ b1) {
    __shared__ float sW[64 * 128];
    __shared__ float sh[8][64];
    int tid = threadIdx.x;
    for (int i = tid; i < 8192; i += 256) sW[i] = W2[i];
    int warp = tid >> 5, lane = tid & 31;
    int node = blockIdx.x * 8 + warp;
    float a0 = fmaxf(d_acc1[(size_t)node * 64 + lane] + b1[lane], 0.0f);
    float a1 = fmaxf(d_acc1[(size_t)node * 64 + 32 + lane] + b1[32 + lane], 0.0f);
    sh[warp][lane] = a0;
    sh[warp][32 + lane] = a1;
    __syncthreads();
    float o0 = 0.f, o1 = 0.f, o2 = 0.f, o3 = 0.f;
#pragma unroll
    for (int k = 0; k < 64; k++) {
        float hk = sh[warp][k];
        const float* w = sW + k * 128 + lane;
        o0 = fmaf(hk, w[0],  o0);
        o1 = fmaf(hk, w[32], o1);
        o2 = fmaf(hk, w[64], o2);
        o3 = fmaf(hk, w[96], o3);
    }
    float di = d_dinv[node];
    size_t b = (size_t)node * 128 + lane;
    d_g2[b]        = di * o0;
    d_g2[b + 32]   = di * o1;
    d_g2[b + 64]   = di * o2;
    d_g2[b + 96]   = di * o3;
    float d2 = di * di;
    d_acc2[b]      = d2 * o0;
    d_acc2[b + 32] = d2 * o1;
    d_acc2[b + 64] = d2 * o2;
    d_acc2[b + 96] = d2 * o3;
}

// ---- K6: edge scatter, 128 feats. 32 threads/edge (1 warp), one float4 each ----
__global__ void k_edge128(const void* __restrict__ ei) {
    long long t = (long long)blockIdx.x * blockDim.x + threadIdx.x;
    int e = (int)(t >> 5);
    int q = (int)(t & 31);
    if (e >= NE) return;
    int src = load_idx(ei, e);
    int dst = load_idx(ei, (long long)NE + e);
    float nd = d_dinv[dst];
    const float4* gp = (const float4*)(d_g2 + (size_t)src * 128);
    float4 v = gp[q];
    float* ap = d_acc2 + (size_t)dst * 128 + q * 4;
    asm volatile("red.global.add.v4.f32 [%0], {%1,%2,%3,%4};"
                 :: "l"(ap), "f"(v.x * nd), "f"(v.y * nd), "f"(v.z * nd), "f"(v.w * nd)
                 : "memory");
}

// ---- K7a: zero output + counts ----
__global__ void k_zero(float* __restrict__ out) {
    int i = blockIdx.x * blockDim.x + threadIdx.x;
    if (i < NG * NG) out[i] = 0.0f;
    if (i < NG) d_cnt[i] = 0.0f;
}

// ---- K7b: per-graph node counts ----
__global__ void k_cnt(const void* __restrict__ batch) {
    int i = blockIdx.x * blockDim.x + threadIdx.x;
    if (i < NN) {
        int g = load_idx(batch, i);
        atomicAdd(&d_cnt[g], 1.0f);
    }
}

// ---- K7c: pooling sum. batch is sorted: block handles 32 consecutive nodes,
// thread = feature column; flush accumulator on graph change. ----
__global__ void k_pool(const void* __restrict__ batch, float* __restrict__ out) {
    int c = threadIdx.x;            // 0..127
    int n0 = blockIdx.x * 32;
    int cur = load_idx(batch, n0);
    float s = 0.0f;
    for (int j = 0; j < 32; j++) {
        int i = n0 + j;
        int g = load_idx(batch, i);
        if (g != cur) {
            atomicAdd(&out[cur * 128 + c], s);
            s = 0.0f;
            cur = g;
        }
        s += d_acc2[(size_t)i * 128 + c];
    }
    atomicAdd(&out[cur * 128 + c], s);
}

// ---- K7d: divide by counts, add b2 (pool of (h2+b2) == mean(h2)+b2) ----
__global__ void k_final(float* __restrict__ out, const float* __restrict__ b2) {
    int i = blockIdx.x * blockDim.x + threadIdx.x;
    if (i < NG * NG) {
        int g = i >> 7, c = i & 127;
        out[i] = out[i] / fmaxf(d_cnt[g], 1.0f) + b2[c];
    }
}

extern "C" void kernel_launch(void* const* d_in, const int* in_sizes, int n_in,
                              void* d_out, int out_size) {
    const float* x     = (const float*)d_in[0];
    const void*  ei    = d_in[1];             // int64 or int32, probed at runtime
    const void*  batch = d_in[2];
    const float* W1    = (const float*)d_in[3];
    const float* b1    = (const float*)d_in[4];
    const float* W2    = (const float*)d_in[5];
    const float* b2    = (const float*)d_in[6];
    float* out = (float*)d_out;

    k_probe<<<1, 32>>>(ei);
    k_init_deg<<<(NN + 255) / 256, 256>>>();
    k_deg<<<(NE + 255) / 256, 256>>>(ei);
    k_node1<<<NN / 4, 256>>>(x, W1);
    k_edge64<<<(NE * 16) / 256, 256>>>(ei);
    k_node2<<<NN / 8, 256>>>(W2, b1);
    k_edge128<<<((long long)NE * 32) / 256, 256>>>(ei);
    k_zero<<<(NG * NG + 255) / 256, 256>>>(out);
    k_cnt<<<(NN + 255) / 256, 256>>>(batch);
    k_pool<<<NN / 32, 128>>>(batch, out);
    k_final<<<(NG * NG + 255) / 256, 256>>>(out, b2);
}